// round 3
// baseline (speedup 1.0000x reference)
#include <cuda_runtime.h>
#include <cuda_bf16.h>
#include <math.h>

// Problem constants
#define BATCH 8
#define SEQ   8192
#define DIM   512
#define HEADS 8
#define DH    64
#define SL    32
#define MTOT  (BATCH * SEQ)          // 65536 rows
#define KV_SPLITS 64

// ---------------- device scratch ----------------
__device__ float g_xmid[(size_t)MTOT * DIM];
__device__ float g_u   [(size_t)MTOT * DIM];
__device__ float g_S1p [(size_t)KV_SPLITS * 64 * SL * DH];
__device__ float g_S0p [(size_t)KV_SPLITS * 64 * SL];
__device__ float g_kv  [(size_t)64 * SL * DH];

__device__ __forceinline__ unsigned f2tf32(float f) {
    unsigned u;
    asm("cvt.rna.tf32.f32 %0, %1;" : "=r"(u) : "f"(f));
    return u;
}
__device__ __forceinline__ float tf32r(float f) { return __uint_as_float(f2tf32(f)); }
__device__ __forceinline__ float4 tf32r4(float4 v) {
    float4 o; o.x = tf32r(v.x); o.y = tf32r(v.y); o.z = tf32r(v.z); o.w = tf32r(v.w);
    return o;
}
__device__ __forceinline__ void mma_tf32(float* c, const unsigned* a, const unsigned* b) {
    asm volatile(
        "mma.sync.aligned.m16n8k8.row.col.f32.tf32.tf32.f32 "
        "{%0,%1,%2,%3}, {%4,%5,%6,%7}, {%8,%9}, {%0,%1,%2,%3};"
        : "+f"(c[0]), "+f"(c[1]), "+f"(c[2]), "+f"(c[3])
        : "r"(a[0]), "r"(a[1]), "r"(a[2]), "r"(a[3]), "r"(b[0]), "r"(b[1]));
}

// ---------------- Kernel 1/5: TF32 GEMM, 256x128 tile, BK=8, double-buffered ----------------
// 256 threads = 8 warps (4 row x 2 col), warp tile 64x64 (4 mt x 8 nt m16n8k8).
__global__ __launch_bounds__(256) void tf32gemm_bias_kernel(
    const float* __restrict__ A, const float* __restrict__ W,
    const float* __restrict__ bias, float* __restrict__ C)
{
    const int K = 512, N = 512;
    __shared__ float As[2][256][12];   // stride 12: (12g+t)%32 all-distinct for A frags
    __shared__ float Bs[2][8][136];    // stride 136: (8t+g)%32 all-distinct for B frags

    const int tid  = threadIdx.x;
    const int warp = tid >> 5;
    const int lane = tid & 31;
    const int g = lane >> 2;
    const int t = lane & 3;

    const int rowBase = blockIdx.y * 256;
    const int colBase = blockIdx.x * 128;
    const int wm = (warp >> 1) * 64;
    const int wn = (warp & 1) * 64;

    float acc[4][8][4];
#pragma unroll
    for (int mt = 0; mt < 4; mt++)
#pragma unroll
        for (int nt = 0; nt < 8; nt++)
#pragma unroll
            for (int i = 0; i < 4; i++) acc[mt][nt][i] = 0.f;

    // global load mapping
    const int aRow = tid >> 1;            // 0..127 (second half +128)
    const int aC4  = (tid & 1) * 4;
    const int bRow = tid >> 5;            // 0..7
    const int bC4  = (tid & 31) * 4;

    const float* Abase = A + (size_t)(rowBase + aRow) * K + aC4;
    const float* Abase2 = Abase + (size_t)128 * K;
    const float* Bbase = W + (size_t)bRow * N + colBase + bC4;

    // prologue: tile 0 -> buf 0
    {
        float4 a0 = *reinterpret_cast<const float4*>(Abase);
        float4 a1 = *reinterpret_cast<const float4*>(Abase2);
        float4 b0 = *reinterpret_cast<const float4*>(Bbase);
        *reinterpret_cast<float4*>(&As[0][aRow][aC4])       = tf32r4(a0);
        *reinterpret_cast<float4*>(&As[0][aRow + 128][aC4]) = tf32r4(a1);
        *reinterpret_cast<float4*>(&Bs[0][bRow][bC4])       = tf32r4(b0);
    }
    __syncthreads();

    int cur = 0;
#pragma unroll 1
    for (int kt = 0; kt < K; kt += 8) {
        const bool nxt = (kt + 8) < K;
        float4 a0, a1, b0;
        if (nxt) {
            a0 = *reinterpret_cast<const float4*>(Abase + kt + 8);
            a1 = *reinterpret_cast<const float4*>(Abase2 + kt + 8);
            b0 = *reinterpret_cast<const float4*>(Bbase + (size_t)(kt + 8) * N);
        }

        // fragments from buf cur
        unsigned af[4][4], bf[8][2];
#pragma unroll
        for (int mt = 0; mt < 4; mt++) {
            const int r0 = wm + mt * 16 + g;
            af[mt][0] = __float_as_uint(As[cur][r0    ][t    ]);
            af[mt][1] = __float_as_uint(As[cur][r0 + 8][t    ]);
            af[mt][2] = __float_as_uint(As[cur][r0    ][t + 4]);
            af[mt][3] = __float_as_uint(As[cur][r0 + 8][t + 4]);
        }
#pragma unroll
        for (int nt = 0; nt < 8; nt++) {
            const int c0 = wn + nt * 8 + g;
            bf[nt][0] = __float_as_uint(Bs[cur][t    ][c0]);
            bf[nt][1] = __float_as_uint(Bs[cur][t + 4][c0]);
        }
#pragma unroll
        for (int mt = 0; mt < 4; mt++)
#pragma unroll
            for (int nt = 0; nt < 8; nt++)
                mma_tf32(acc[mt][nt], af[mt], bf[nt]);

        if (nxt) {
            const int nb = cur ^ 1;
            *reinterpret_cast<float4*>(&As[nb][aRow][aC4])       = tf32r4(a0);
            *reinterpret_cast<float4*>(&As[nb][aRow + 128][aC4]) = tf32r4(a1);
            *reinterpret_cast<float4*>(&Bs[nb][bRow][bC4])       = tf32r4(b0);
        }
        __syncthreads();
        cur ^= 1;
    }

    // epilogue: bias + store
#pragma unroll
    for (int nt = 0; nt < 8; nt++) {
        const int col = colBase + wn + nt * 8 + 2 * t;
        const float bx = bias[col], by = bias[col + 1];
#pragma unroll
        for (int mt = 0; mt < 4; mt++) {
            const int row0 = rowBase + wm + mt * 16 + g;
            float2 o0, o1;
            o0.x = acc[mt][nt][0] + bx; o0.y = acc[mt][nt][1] + by;
            o1.x = acc[mt][nt][2] + bx; o1.y = acc[mt][nt][3] + by;
            *reinterpret_cast<float2*>(&C[(size_t)row0 * N + col])       = o0;
            *reinterpret_cast<float2*>(&C[(size_t)(row0 + 8) * N + col]) = o1;
        }
    }
}

// ---------------- Kernel 2: kv accumulate (unchanged) ----------------
__global__ __launch_bounds__(256) void kv_accum_kernel(
    const float* __restrict__ xmid, const float* __restrict__ Wk,
    const float* __restrict__ Wv)
{
    const int split = blockIdx.x;
    const int h = blockIdx.y;
    const int b = blockIdx.z;
    const int bh = b * HEADS + h;
    const int tid = threadIdx.x;

    __shared__ float Wks[64][32];
    __shared__ float Wvs[64][64];
    __shared__ float Xs[32][65];
    __shared__ float Es[32][33];
    __shared__ float Vs[32][65];

    for (int idx = tid; idx < 64 * 32; idx += 256) Wks[idx >> 5][idx & 31] = Wk[idx];
    for (int idx = tid; idx < 64 * 64; idx += 256) Wvs[idx >> 6][idx & 63] = Wv[idx];

    const int s_own = tid >> 3;
    const int c_own = (tid & 7) * 8;
    float acc[8];
#pragma unroll
    for (int i = 0; i < 8; i++) acc[i] = 0.f;
    float s0acc = 0.f;

    for (int chunk = 0; chunk < 4; chunk++) {
        const int n0 = split * 128 + chunk * 32;
        __syncthreads();

        for (int idx = tid; idx < 32 * 64; idx += 256) {
            int r = idx >> 6, c = idx & 63;
            Xs[r][c] = xmid[(size_t)(b * SEQ + n0 + r) * DIM + h * DH + c];
        }
        __syncthreads();

        for (int idx = tid; idx < 32 * 96; idx += 256) {
            int r = idx / 96;
            int j = idx - r * 96;
            float d = 0.f;
            if (j < 32) {
#pragma unroll
                for (int tt = 0; tt < 64; tt++) d = fmaf(Xs[r][tt], Wks[tt][j], d);
                Es[r][j] = expf(d);
            } else {
                int c = j - 32;
#pragma unroll
                for (int tt = 0; tt < 64; tt++) d = fmaf(Xs[r][tt], Wvs[tt][c], d);
                Vs[r][c] = d;
            }
        }
        __syncthreads();

#pragma unroll 4
        for (int r = 0; r < 32; r++) {
            float e = Es[r][s_own];
            const float* vp = &Vs[r][c_own];
#pragma unroll
            for (int i = 0; i < 8; i++) acc[i] = fmaf(e, vp[i], acc[i]);
        }
        if (tid < 32) {
#pragma unroll 4
            for (int r = 0; r < 32; r++) s0acc += Es[r][tid];
        }
    }

    float* s1p = g_S1p + ((size_t)split * 64 + bh) * (SL * DH) + tid * 8;
#pragma unroll
    for (int i = 0; i < 8; i++) s1p[i] = acc[i];
    if (tid < 32) g_S0p[((size_t)split * 64 + bh) * SL + tid] = s0acc;
}

// ---------------- Kernel 3: kv finalize ----------------
__global__ __launch_bounds__(256) void kv_final_kernel()
{
    int idx = blockIdx.x * 256 + threadIdx.x;
    if (idx >= 64 * SL * DH) return;
    int bh = idx >> 11;
    int sc = idx & 2047;
    int s  = sc >> 6;
    float s1 = 0.f, s0 = 0.f;
    for (int sp = 0; sp < KV_SPLITS; sp++) {
        s1 += g_S1p[((size_t)sp * 64 + bh) * (SL * DH) + sc];
        s0 += g_S0p[((size_t)sp * 64 + bh) * SL + s];
    }
    g_kv[idx] = s1 / s0;
}

// ---------------- Kernel 4: qkv via tensor cores ----------------
// Block: 64 tokens x 1 head, 128 threads (4 warps). Warp w owns rows 16w..16w+15.
// Phase 1: Q = X(64x64) @ Wq(64x32) (mma). Softmax rows. Phase 2: U = Q @ kv(32x64) (mma).
__global__ __launch_bounds__(128) void qkv_kernel(
    const float* __restrict__ xmid, const float* __restrict__ Wq)
{
    const int tile = blockIdx.x;
    const int h = blockIdx.y;
    const int b = blockIdx.z;
    const int bh = b * HEADS + h;
    const int tid = threadIdx.x;
    const int w = tid >> 5;
    const int lane = tid & 31;
    const int g = lane >> 2;
    const int t = lane & 3;
    const int n0 = tile * 64;

    __shared__ float Xs[64][68];   // stride%32=4 -> A-frag conflict-free
    __shared__ float Wqs[64][40];  // stride%32=8 -> B-frag conflict-free
    __shared__ float kvs[32][72];  // stride%32=8 -> B-frag conflict-free
    __shared__ float Qs[64][36];   // stride%32=4 -> A-frag conflict-free

    // loads (tf32-rounded)
    for (int idx = tid; idx < 64 * 16; idx += 128) {          // X: 64x64 as float4
        int r = idx >> 4, c4 = (idx & 15) * 4;
        float4 v = *reinterpret_cast<const float4*>(
            &xmid[(size_t)(b * SEQ + n0 + r) * DIM + h * DH + c4]);
        *reinterpret_cast<float4*>(&Xs[r][c4]) = tf32r4(v);
    }
    for (int idx = tid; idx < 64 * 32; idx += 128)            // Wq: 64x32
        Wqs[idx >> 5][idx & 31] = tf32r(Wq[idx]);
    for (int idx = tid; idx < SL * DH; idx += 128)            // kv: 32x64
        kvs[idx >> 6][idx & 63] = tf32r(g_kv[(size_t)bh * (SL * DH) + idx]);
    __syncthreads();

    // Phase 1: Q = X @ Wq  (warp: 16x32 = 4 nt tiles, k=64 -> 8 ks)
    {
        float qacc[4][4];
#pragma unroll
        for (int nt = 0; nt < 4; nt++)
#pragma unroll
            for (int i = 0; i < 4; i++) qacc[nt][i] = 0.f;

#pragma unroll
        for (int ks = 0; ks < 8; ks++) {
            const int r0 = 16 * w + g;
            unsigned af[4];
            af[0] = __float_as_uint(Xs[r0    ][8 * ks + t    ]);
            af[1] = __float_as_uint(Xs[r0 + 8][8 * ks + t    ]);
            af[2] = __float_as_uint(Xs[r0    ][8 * ks + t + 4]);
            af[3] = __float_as_uint(Xs[r0 + 8][8 * ks + t + 4]);
#pragma unroll
            for (int nt = 0; nt < 4; nt++) {
                unsigned bf[2];
                bf[0] = __float_as_uint(Wqs[8 * ks + t    ][nt * 8 + g]);
                bf[1] = __float_as_uint(Wqs[8 * ks + t + 4][nt * 8 + g]);
                mma_tf32(qacc[nt], af, bf);
            }
        }
        // write Q frags to smem
#pragma unroll
        for (int nt = 0; nt < 4; nt++) {
            const int r0 = 16 * w + g, c0 = nt * 8 + 2 * t;
            Qs[r0    ][c0]     = qacc[nt][0];
            Qs[r0    ][c0 + 1] = qacc[nt][1];
            Qs[r0 + 8][c0]     = qacc[nt][2];
            Qs[r0 + 8][c0 + 1] = qacc[nt][3];
        }
    }
    __syncthreads();

    // softmax over slice dim (one token per thread), store tf32-rounded
    if (tid < 64) {
        float m = Qs[tid][0];
#pragma unroll
        for (int s = 1; s < 32; s++) m = fmaxf(m, Qs[tid][s]);
        float e[32], sum = 0.f;
#pragma unroll
        for (int s = 0; s < 32; s++) { e[s] = expf(Qs[tid][s] - m); sum += e[s]; }
        float inv = 1.f / sum;
#pragma unroll
        for (int s = 0; s < 32; s++) Qs[tid][s] = tf32r(e[s] * inv);
    }
    __syncthreads();

    // Phase 2: U = Q(64x32) @ kv(32x64)  (warp: 16x64 = 8 nt tiles, k=32 -> 4 ks)
    {
        float oacc[8][4];
#pragma unroll
        for (int nt = 0; nt < 8; nt++)
#pragma unroll
            for (int i = 0; i < 4; i++) oacc[nt][i] = 0.f;

#pragma unroll
        for (int ks = 0; ks < 4; ks++) {
            const int r0 = 16 * w + g;
            unsigned af[4];
            af[0] = __float_as_uint(Qs[r0    ][8 * ks + t    ]);
            af[1] = __float_as_uint(Qs[r0 + 8][8 * ks + t    ]);
            af[2] = __float_as_uint(Qs[r0    ][8 * ks + t + 4]);
            af[3] = __float_as_uint(Qs[r0 + 8][8 * ks + t + 4]);
#pragma unroll
            for (int nt = 0; nt < 8; nt++) {
                unsigned bf[2];
                bf[0] = __float_as_uint(kvs[8 * ks + t    ][nt * 8 + g]);
                bf[1] = __float_as_uint(kvs[8 * ks + t + 4][nt * 8 + g]);
                mma_tf32(oacc[nt], af, bf);
            }
        }
        // store to g_u
        const int row0 = b * SEQ + n0 + 16 * w + g;
#pragma unroll
        for (int nt = 0; nt < 8; nt++) {
            const int col = h * DH + nt * 8 + 2 * t;
            float2 o0, o1;
            o0.x = oacc[nt][0]; o0.y = oacc[nt][1];
            o1.x = oacc[nt][2]; o1.y = oacc[nt][3];
            *reinterpret_cast<float2*>(&g_u[(size_t)row0 * DIM + col])       = o0;
            *reinterpret_cast<float2*>(&g_u[(size_t)(row0 + 8) * DIM + col]) = o1;
        }
    }
}

// ---------------- launch ----------------
extern "C" void kernel_launch(void* const* d_in, const int* in_sizes, int n_in,
                              void* d_out, int out_size)
{
    const float* x     = (const float*)d_in[0];
    const float* W_in  = (const float*)d_in[1];
    const float* b_in  = (const float*)d_in[2];
    const float* Wq    = (const float*)d_in[3];
    const float* Wk    = (const float*)d_in[4];
    const float* Wv    = (const float*)d_in[5];
    const float* W_out = (const float*)d_in[6];
    const float* b_out = (const float*)d_in[7];
    float* out = (float*)d_out;

    float *xmid, *u;
    cudaGetSymbolAddress((void**)&xmid, g_xmid);
    cudaGetSymbolAddress((void**)&u, g_u);

    dim3 gemmGrid(DIM / 128, MTOT / 256);

    tf32gemm_bias_kernel<<<gemmGrid, 256>>>(x, W_in, b_in, xmid);

    dim3 kvGrid(KV_SPLITS, HEADS, BATCH);
    kv_accum_kernel<<<kvGrid, 256>>>(xmid, Wk, Wv);

    kv_final_kernel<<<(64 * SL * DH + 255) / 256, 256>>>();

    dim3 qGrid(SEQ / 64, HEADS, BATCH);
    qkv_kernel<<<qGrid, 128>>>(xmid, Wq);

    tf32gemm_bias_kernel<<<gemmGrid, 256>>>(u, W_out, b_out, out);
}

// round 4
// speedup vs baseline: 2.2428x; 2.2428x over previous
#include <cuda_runtime.h>
#include <cuda_bf16.h>
#include <math.h>

#define BATCH 8
#define SEQ   8192
#define DIM   512
#define HEADS 8
#define DH    64
#define SL    32
#define MTOT  (BATCH * SEQ)
#define KV_SPLITS 64

// ---------------- device scratch ----------------
__device__ float g_xmid[(size_t)MTOT * DIM];
__device__ float g_u   [(size_t)MTOT * DIM];
__device__ float g_S1p [(size_t)KV_SPLITS * 64 * SL * DH];
__device__ float g_S0p [(size_t)KV_SPLITS * 64 * SL];
__device__ float g_kv  [(size_t)64 * SL * DH];

__device__ __forceinline__ unsigned f2tf32(float f) {
    unsigned u;
    asm("cvt.rna.tf32.f32 %0, %1;" : "=r"(u) : "f"(f));
    return u;
}
__device__ __forceinline__ float tf32r(float f) { return __uint_as_float(f2tf32(f)); }
__device__ __forceinline__ float4 tf32r4(float4 v) {
    float4 o; o.x = tf32r(v.x); o.y = tf32r(v.y); o.z = tf32r(v.z); o.w = tf32r(v.w);
    return o;
}
__device__ __forceinline__ void mma_tf32(float* c, const unsigned* a, const unsigned* b) {
    asm volatile(
        "mma.sync.aligned.m16n8k8.row.col.f32.tf32.tf32.f32 "
        "{%0,%1,%2,%3}, {%4,%5,%6,%7}, {%8,%9}, {%0,%1,%2,%3};"
        : "+f"(c[0]), "+f"(c[1]), "+f"(c[2]), "+f"(c[3])
        : "r"(a[0]), "r"(a[1]), "r"(a[2]), "r"(a[3]), "r"(b[0]), "r"(b[1]));
}

__device__ __forceinline__ unsigned smem_u32(const void* p) {
    return (unsigned)__cvta_generic_to_shared(p);
}
#define CP16(dst, src) asm volatile("cp.async.cg.shared.global [%0], [%1], 16;" :: "r"(dst), "l"(src))
#define CP_COMMIT()    asm volatile("cp.async.commit_group;")
#define CP_WAIT1()     asm volatile("cp.async.wait_group 1;")
#define CP_WAIT0()     asm volatile("cp.async.wait_group 0;")

// ---------------- Kernel 1/5: TF32 GEMM, 128x128 tile, BK=16, cp.async 2-stage ----------------
// 256 threads = 8 warps (4 row x 2 col), warp tile 32x64 (2 mt x 8 nt).
__global__ __launch_bounds__(256) void tf32gemm_bias_kernel(
    const float* __restrict__ A, const float* __restrict__ W,
    const float* __restrict__ bias, float* __restrict__ C)
{
    const int K = 512, N = 512;
    __shared__ float As[2][128][20];   // (20g+t)%32 distinct -> A-frag conflict-free
    __shared__ float Bs[2][16][136];   // (136t+g)%32 = (8t+g)%32 distinct -> B-frag conflict-free

    const int tid  = threadIdx.x;
    const int warp = tid >> 5;
    const int lane = tid & 31;
    const int g = lane >> 2;
    const int t = lane & 3;

    const int rowBase = blockIdx.y * 128;
    const int colBase = blockIdx.x * 128;
    const int wm = (warp & 3) * 32;
    const int wn = (warp >> 2) * 64;

    float acc[2][8][4];
#pragma unroll
    for (int mt = 0; mt < 2; mt++)
#pragma unroll
        for (int nt = 0; nt < 8; nt++)
#pragma unroll
            for (int i = 0; i < 4; i++) acc[mt][nt][i] = 0.f;

    // cp.async mapping: A 128x16 (rows tid>>2 and +64), B 16x128 (rows tid>>5 and +8)
    const int aRow = tid >> 2;
    const int aC4  = (tid & 3) * 4;
    const int bRow = tid >> 5;
    const int bC4  = (tid & 31) * 4;

    const float* Ag  = A + (size_t)(rowBase + aRow) * K + aC4;
    const float* Ag2 = Ag + (size_t)64 * K;
    const float* Bg  = W + (size_t)bRow * N + colBase + bC4;
    const float* Bg2 = Bg + (size_t)8 * N;

    unsigned sA0 = smem_u32(&As[0][aRow][aC4]);
    unsigned sA1 = smem_u32(&As[0][aRow + 64][aC4]);
    unsigned sB0 = smem_u32(&Bs[0][bRow][bC4]);
    unsigned sB1 = smem_u32(&Bs[0][bRow + 8][bC4]);
    const unsigned strideA = 128 * 20 * 4;   // bytes per A stage
    const unsigned strideB = 16 * 136 * 4;   // bytes per B stage

    // prologue: stage 0
    CP16(sA0, Ag);  CP16(sA1, Ag2);
    CP16(sB0, Bg);  CP16(sB1, Bg2);
    CP_COMMIT();

#pragma unroll 1
    for (int it = 0; it < 32; it++) {
        const int kt = it * 16;
        const int cur = it & 1;
        if (it + 1 < 32) {
            const unsigned off = (cur ^ 1) ? (strideA) : 0;
            const unsigned offB = (cur ^ 1) ? (strideB) : 0;
            CP16(sA0 + off, Ag + kt + 16);
            CP16(sA1 + off, Ag2 + kt + 16);
            CP16(sB0 + offB, Bg + (size_t)(kt + 16) * N);
            CP16(sB1 + offB, Bg2 + (size_t)(kt + 16) * N);
            CP_COMMIT();
            CP_WAIT1();
        } else {
            CP_WAIT0();
        }
        __syncthreads();

#pragma unroll
        for (int ks = 0; ks < 16; ks += 8) {
            unsigned af[2][4], bf[8][2];
#pragma unroll
            for (int mt = 0; mt < 2; mt++) {
                const int r0 = wm + mt * 16 + g;
                af[mt][0] = f2tf32(As[cur][r0    ][ks + t    ]);
                af[mt][1] = f2tf32(As[cur][r0 + 8][ks + t    ]);
                af[mt][2] = f2tf32(As[cur][r0    ][ks + t + 4]);
                af[mt][3] = f2tf32(As[cur][r0 + 8][ks + t + 4]);
            }
#pragma unroll
            for (int nt = 0; nt < 8; nt++) {
                const int c0 = wn + nt * 8 + g;
                bf[nt][0] = f2tf32(Bs[cur][ks + t    ][c0]);
                bf[nt][1] = f2tf32(Bs[cur][ks + t + 4][c0]);
            }
#pragma unroll
            for (int mt = 0; mt < 2; mt++)
#pragma unroll
                for (int nt = 0; nt < 8; nt++)
                    mma_tf32(acc[mt][nt], af[mt], bf[nt]);
        }
        __syncthreads();   // protect buf cur before it is overwritten at it+2
    }

    // epilogue
#pragma unroll
    for (int nt = 0; nt < 8; nt++) {
        const int col = colBase + wn + nt * 8 + 2 * t;
        const float bx = bias[col], by = bias[col + 1];
#pragma unroll
        for (int mt = 0; mt < 2; mt++) {
            const int row0 = rowBase + wm + mt * 16 + g;
            float2 o0, o1;
            o0.x = acc[mt][nt][0] + bx; o0.y = acc[mt][nt][1] + by;
            o1.x = acc[mt][nt][2] + bx; o1.y = acc[mt][nt][3] + by;
            *reinterpret_cast<float2*>(&C[(size_t)row0 * N + col])       = o0;
            *reinterpret_cast<float2*>(&C[(size_t)(row0 + 8) * N + col]) = o1;
        }
    }
}

// ---------------- Kernel 2: kv accumulate via tensor cores ----------------
// 128 threads (4 warps). Block handles 128 tokens (2 chunks of 64) for one (b,h,split).
// Phase A: P = X(64x64) @ [Wk|Wv](64x96) mma; E = exp(P[:, :32]) stored transposed; V = P[:,32:96].
// Phase B: S1 += E(32x64tok) @ V(64tok x 64) mma; S0 += column sums of E.
__global__ __launch_bounds__(128) void kv_accum_kernel(
    const float* __restrict__ xmid, const float* __restrict__ Wk,
    const float* __restrict__ Wv)
{
    const int split = blockIdx.x;
    const int h = blockIdx.y;
    const int b = blockIdx.z;
    const int bh = b * HEADS + h;
    const int tid = threadIdx.x;
    const int w = tid >> 5;
    const int lane = tid & 31;
    const int g = lane >> 2;
    const int t = lane & 3;

    __shared__ float Ws[64][104];  // cols 0-31 Wk, 32-95 Wv; stride%32=8 (B-frag ok)
    __shared__ float Xs[64][68];   // stride%32=4 (A-frag ok)
    __shared__ float Es[32][68];   // E transposed [slice][token]; stride%32=4 (A-frag ok)
    __shared__ float Vs[64][72];   // [token][channel]; stride%32=8 (B-frag ok)

    for (int idx = tid; idx < 64 * 32; idx += 128) Ws[idx >> 5][idx & 31] = tf32r(Wk[idx]);
    for (int idx = tid; idx < 64 * 64; idx += 128) Ws[idx >> 6][32 + (idx & 63)] = tf32r(Wv[idx]);
    __syncthreads();

    // weight B-fragments in registers: warp w owns cols [24w, 24w+24)
    unsigned bfw[3][8][2];
#pragma unroll
    for (int nt = 0; nt < 3; nt++)
#pragma unroll
        for (int ks = 0; ks < 8; ks++) {
            const int c0 = 24 * w + nt * 8 + g;
            bfw[nt][ks][0] = __float_as_uint(Ws[8 * ks + t    ][c0]);
            bfw[nt][ks][1] = __float_as_uint(Ws[8 * ks + t + 4][c0]);
        }

    float accS1[2][2][4];
#pragma unroll
    for (int mt = 0; mt < 2; mt++)
#pragma unroll
        for (int nt = 0; nt < 2; nt++)
#pragma unroll
            for (int i = 0; i < 4; i++) accS1[mt][nt][i] = 0.f;
    float s0acc = 0.f;

#pragma unroll 1
    for (int chunk = 0; chunk < 2; chunk++) {
        const int n0 = split * 128 + chunk * 64;
        __syncthreads();   // prior accum-mma / S0 reads of Es,Vs done; Xs reusable

        for (int idx = tid; idx < 64 * 16; idx += 128) {
            int r = idx >> 4, c4 = (idx & 15) * 4;
            float4 v = *reinterpret_cast<const float4*>(
                &xmid[(size_t)(b * SEQ + n0 + r) * DIM + h * DH + c4]);
            *reinterpret_cast<float4*>(&Xs[r][c4]) = tf32r4(v);
        }
        __syncthreads();

        // projection mma: all 64 rows (4 mt) x warp's 24 cols (3 nt)
        float pacc[4][3][4];
#pragma unroll
        for (int mt = 0; mt < 4; mt++)
#pragma unroll
            for (int nt = 0; nt < 3; nt++)
#pragma unroll
                for (int i = 0; i < 4; i++) pacc[mt][nt][i] = 0.f;

#pragma unroll
        for (int ks = 0; ks < 8; ks++) {
            unsigned af[4][4];
#pragma unroll
            for (int mt = 0; mt < 4; mt++) {
                const int r0 = mt * 16 + g;
                af[mt][0] = __float_as_uint(Xs[r0    ][8 * ks + t    ]);
                af[mt][1] = __float_as_uint(Xs[r0 + 8][8 * ks + t    ]);
                af[mt][2] = __float_as_uint(Xs[r0    ][8 * ks + t + 4]);
                af[mt][3] = __float_as_uint(Xs[r0 + 8][8 * ks + t + 4]);
            }
#pragma unroll
            for (int mt = 0; mt < 4; mt++)
#pragma unroll
                for (int nt = 0; nt < 3; nt++)
                    mma_tf32(pacc[mt][nt], af[mt], bfw[nt][ks]);
        }

        // epilogue: exp -> Es (transposed), V -> Vs
#pragma unroll
        for (int mt = 0; mt < 4; mt++)
#pragma unroll
            for (int nt = 0; nt < 3; nt++) {
                const int c0 = 24 * w + nt * 8 + 2 * t;
                const int r0 = mt * 16 + g;
                float v0 = pacc[mt][nt][0], v1 = pacc[mt][nt][1];
                float v2 = pacc[mt][nt][2], v3 = pacc[mt][nt][3];
                if (c0 < 32) {
                    Es[c0    ][r0]     = tf32r(expf(v0));
                    Es[c0 + 1][r0]     = tf32r(expf(v1));
                    Es[c0    ][r0 + 8] = tf32r(expf(v2));
                    Es[c0 + 1][r0 + 8] = tf32r(expf(v3));
                } else {
                    Vs[r0    ][c0 - 32]     = tf32r(v0);
                    Vs[r0    ][c0 - 32 + 1] = tf32r(v1);
                    Vs[r0 + 8][c0 - 32]     = tf32r(v2);
                    Vs[r0 + 8][c0 - 32 + 1] = tf32r(v3);
                }
            }
        __syncthreads();

        // S0: column sums of E (slice s = tid for tid<32)
        if (tid < 32) {
            float s = 0.f;
#pragma unroll
            for (int r = 0; r < 64; r++) s += Es[tid][r];
            s0acc += s;
        }

        // accumulate mma: S1(32x64) += E(32x64tok) @ V(64tok x 64); warp w: cols [16w,16w+16)
#pragma unroll
        for (int ks = 0; ks < 8; ks++) {
            unsigned af2[2][4];
#pragma unroll
            for (int mt = 0; mt < 2; mt++) {
                const int r0 = mt * 16 + g;
                af2[mt][0] = __float_as_uint(Es[r0    ][8 * ks + t    ]);
                af2[mt][1] = __float_as_uint(Es[r0 + 8][8 * ks + t    ]);
                af2[mt][2] = __float_as_uint(Es[r0    ][8 * ks + t + 4]);
                af2[mt][3] = __float_as_uint(Es[r0 + 8][8 * ks + t + 4]);
            }
#pragma unroll
            for (int nt = 0; nt < 2; nt++) {
                const int c0 = 16 * w + nt * 8 + g;
                unsigned bf2[2];
                bf2[0] = __float_as_uint(Vs[8 * ks + t    ][c0]);
                bf2[1] = __float_as_uint(Vs[8 * ks + t + 4][c0]);
#pragma unroll
                for (int mt = 0; mt < 2; mt++)
                    mma_tf32(accS1[mt][nt], af2[mt], bf2);
            }
        }
    }

    // write split partials
    float* base = g_S1p + ((size_t)split * 64 + bh) * (SL * DH);
#pragma unroll
    for (int mt = 0; mt < 2; mt++)
#pragma unroll
        for (int nt = 0; nt < 2; nt++) {
            const int s0 = mt * 16 + g;
            const int c  = 16 * w + nt * 8 + 2 * t;
            base[(s0    ) * DH + c]     = accS1[mt][nt][0];
            base[(s0    ) * DH + c + 1] = accS1[mt][nt][1];
            base[(s0 + 8) * DH + c]     = accS1[mt][nt][2];
            base[(s0 + 8) * DH + c + 1] = accS1[mt][nt][3];
        }
    if (tid < 32) g_S0p[((size_t)split * 64 + bh) * SL + tid] = s0acc;
}

// ---------------- Kernel 3: kv finalize ----------------
__global__ __launch_bounds__(256) void kv_final_kernel()
{
    int idx = blockIdx.x * 256 + threadIdx.x;
    if (idx >= 64 * SL * DH) return;
    int bh = idx >> 11;
    int sc = idx & 2047;
    int s  = sc >> 6;
    float s1 = 0.f, s0 = 0.f;
    for (int sp = 0; sp < KV_SPLITS; sp++) {
        s1 += g_S1p[((size_t)sp * 64 + bh) * (SL * DH) + sc];
        s0 += g_S0p[((size_t)sp * 64 + bh) * SL + s];
    }
    g_kv[idx] = s1 / s0;
}

// ---------------- Kernel 4: qkv via tensor cores (round-3 version, measured 196us) ----------------
__global__ __launch_bounds__(128) void qkv_kernel(
    const float* __restrict__ xmid, const float* __restrict__ Wq)
{
    const int tile = blockIdx.x;
    const int h = blockIdx.y;
    const int b = blockIdx.z;
    const int bh = b * HEADS + h;
    const int tid = threadIdx.x;
    const int w = tid >> 5;
    const int lane = tid & 31;
    const int g = lane >> 2;
    const int t = lane & 3;
    const int n0 = tile * 64;

    __shared__ float Xs[64][68];
    __shared__ float Wqs[64][40];
    __shared__ float kvs[32][72];
    __shared__ float Qs[64][36];

    for (int idx = tid; idx < 64 * 16; idx += 128) {
        int r = idx >> 4, c4 = (idx & 15) * 4;
        float4 v = *reinterpret_cast<const float4*>(
            &xmid[(size_t)(b * SEQ + n0 + r) * DIM + h * DH + c4]);
        *reinterpret_cast<float4*>(&Xs[r][c4]) = tf32r4(v);
    }
    for (int idx = tid; idx < 64 * 32; idx += 128)
        Wqs[idx >> 5][idx & 31] = tf32r(Wq[idx]);
    for (int idx = tid; idx < SL * DH; idx += 128)
        kvs[idx >> 6][idx & 63] = tf32r(g_kv[(size_t)bh * (SL * DH) + idx]);
    __syncthreads();

    {
        float qacc[4][4];
#pragma unroll
        for (int nt = 0; nt < 4; nt++)
#pragma unroll
            for (int i = 0; i < 4; i++) qacc[nt][i] = 0.f;

#pragma unroll
        for (int ks = 0; ks < 8; ks++) {
            const int r0 = 16 * w + g;
            unsigned af[4];
            af[0] = __float_as_uint(Xs[r0    ][8 * ks + t    ]);
            af[1] = __float_as_uint(Xs[r0 + 8][8 * ks + t    ]);
            af[2] = __float_as_uint(Xs[r0    ][8 * ks + t + 4]);
            af[3] = __float_as_uint(Xs[r0 + 8][8 * ks + t + 4]);
#pragma unroll
            for (int nt = 0; nt < 4; nt++) {
                unsigned bf[2];
                bf[0] = __float_as_uint(Wqs[8 * ks + t    ][nt * 8 + g]);
                bf[1] = __float_as_uint(Wqs[8 * ks + t + 4][nt * 8 + g]);
                mma_tf32(qacc[nt], af, bf);
            }
        }
#pragma unroll
        for (int nt = 0; nt < 4; nt++) {
            const int r0 = 16 * w + g, c0 = nt * 8 + 2 * t;
            Qs[r0    ][c0]     = qacc[nt][0];
            Qs[r0    ][c0 + 1] = qacc[nt][1];
            Qs[r0 + 8][c0]     = qacc[nt][2];
            Qs[r0 + 8][c0 + 1] = qacc[nt][3];
        }
    }
    __syncthreads();

    if (tid < 64) {
        float m = Qs[tid][0];
#pragma unroll
        for (int s = 1; s < 32; s++) m = fmaxf(m, Qs[tid][s]);
        float e[32], sum = 0.f;
#pragma unroll
        for (int s = 0; s < 32; s++) { e[s] = expf(Qs[tid][s] - m); sum += e[s]; }
        float inv = 1.f / sum;
#pragma unroll
        for (int s = 0; s < 32; s++) Qs[tid][s] = tf32r(e[s] * inv);
    }
    __syncthreads();

    {
        float oacc[8][4];
#pragma unroll
        for (int nt = 0; nt < 8; nt++)
#pragma unroll
            for (int i = 0; i < 4; i++) oacc[nt][i] = 0.f;

#pragma unroll
        for (int ks = 0; ks < 4; ks++) {
            const int r0 = 16 * w + g;
            unsigned af[4];
            af[0] = __float_as_uint(Qs[r0    ][8 * ks + t    ]);
            af[1] = __float_as_uint(Qs[r0 + 8][8 * ks + t    ]);
            af[2] = __float_as_uint(Qs[r0    ][8 * ks + t + 4]);
            af[3] = __float_as_uint(Qs[r0 + 8][8 * ks + t + 4]);
#pragma unroll
            for (int nt = 0; nt < 8; nt++) {
                unsigned bf[2];
                bf[0] = __float_as_uint(kvs[8 * ks + t    ][nt * 8 + g]);
                bf[1] = __float_as_uint(kvs[8 * ks + t + 4][nt * 8 + g]);
                mma_tf32(oacc[nt], af, bf);
            }
        }
        const int row0 = b * SEQ + n0 + 16 * w + g;
#pragma unroll
        for (int nt = 0; nt < 8; nt++) {
            const int col = h * DH + nt * 8 + 2 * t;
            float2 o0, o1;
            o0.x = oacc[nt][0]; o0.y = oacc[nt][1];
            o1.x = oacc[nt][2]; o1.y = oacc[nt][3];
            *reinterpret_cast<float2*>(&g_u[(size_t)row0 * DIM + col])       = o0;
            *reinterpret_cast<float2*>(&g_u[(size_t)(row0 + 8) * DIM + col]) = o1;
        }
    }
}

// ---------------- launch ----------------
extern "C" void kernel_launch(void* const* d_in, const int* in_sizes, int n_in,
                              void* d_out, int out_size)
{
    const float* x     = (const float*)d_in[0];
    const float* W_in  = (const float*)d_in[1];
    const float* b_in  = (const float*)d_in[2];
    const float* Wq    = (const float*)d_in[3];
    const float* Wk    = (const float*)d_in[4];
    const float* Wv    = (const float*)d_in[5];
    const float* W_out = (const float*)d_in[6];
    const float* b_out = (const float*)d_in[7];
    float* out = (float*)d_out;

    float *xmid, *u;
    cudaGetSymbolAddress((void**)&xmid, g_xmid);
    cudaGetSymbolAddress((void**)&u, g_u);

    dim3 gemmGrid(DIM / 128, MTOT / 128);

    tf32gemm_bias_kernel<<<gemmGrid, 256>>>(x, W_in, b_in, xmid);

    dim3 kvGrid(KV_SPLITS, HEADS, BATCH);
    kv_accum_kernel<<<kvGrid, 128>>>(xmid, Wk, Wv);

    kv_final_kernel<<<(64 * SL * DH + 255) / 256, 256>>>();

    dim3 qGrid(SEQ / 64, HEADS, BATCH);
    qkv_kernel<<<qGrid, 128>>>(xmid, Wq);

    tf32gemm_bias_kernel<<<gemmGrid, 256>>>(u, W_out, b_out, out);
}

// round 5
// speedup vs baseline: 2.8505x; 1.2710x over previous
#include <cuda_runtime.h>
#include <cuda_bf16.h>
#include <math.h>

#define BATCH 8
#define SEQ   8192
#define DIM   512
#define HEADS 8
#define DH    64
#define SL    32
#define MTOT  (BATCH * SEQ)
#define KV_SPLITS 64
#define QDIM  (HEADS * SL)        // 256

// ---------------- device scratch ----------------
__device__ float g_xmid[(size_t)MTOT * DIM];
__device__ float g_q   [(size_t)MTOT * QDIM];          // softmaxed Q, [n][h*32+s]
__device__ float g_S1p [(size_t)KV_SPLITS * 64 * SL * DH];
__device__ float g_S0p [(size_t)KV_SPLITS * 64 * SL];
__device__ float g_kv  [(size_t)64 * SL * DH];         // [bh][s][c]
__device__ float g_Z   [(size_t)BATCH * QDIM * DIM];   // per-batch Z: [b][h*32+s][n_out]

__device__ __forceinline__ unsigned f2tf32(float f) {
    unsigned u;
    asm("cvt.rna.tf32.f32 %0, %1;" : "=r"(u) : "f"(f));
    return u;
}
__device__ __forceinline__ float tf32r(float f) { return __uint_as_float(f2tf32(f)); }
__device__ __forceinline__ float4 tf32r4(float4 v) {
    float4 o; o.x = tf32r(v.x); o.y = tf32r(v.y); o.z = tf32r(v.z); o.w = tf32r(v.w);
    return o;
}
__device__ __forceinline__ void mma_tf32(float* c, const unsigned* a, const unsigned* b) {
    asm volatile(
        "mma.sync.aligned.m16n8k8.row.col.f32.tf32.tf32.f32 "
        "{%0,%1,%2,%3}, {%4,%5,%6,%7}, {%8,%9}, {%0,%1,%2,%3};"
        : "+f"(c[0]), "+f"(c[1]), "+f"(c[2]), "+f"(c[3])
        : "r"(a[0]), "r"(a[1]), "r"(a[2]), "r"(a[3]), "r"(b[0]), "r"(b[1]));
}

__device__ __forceinline__ unsigned smem_u32(const void* p) {
    return (unsigned)__cvta_generic_to_shared(p);
}
#define CP16(dst, src) asm volatile("cp.async.cg.shared.global [%0], [%1], 16;" :: "r"(dst), "l"(src))
#define CP_COMMIT()    asm volatile("cp.async.commit_group;")
#define CP_WAIT1()     asm volatile("cp.async.wait_group 1;")
#define CP_WAIT0()     asm volatile("cp.async.wait_group 0;")

// ---------------- TF32 GEMM, 128x128 tile, BK=16, cp.async 2-stage, runtime K ----------------
// C[M,512] = A[M,K] @ W[K,512] + bias.  256 threads, 8 warps, warp tile 32x64.
__global__ __launch_bounds__(256) void tf32gemm_bias_kernel(
    const float* __restrict__ A, const float* __restrict__ W,
    const float* __restrict__ bias, float* __restrict__ C, int K)
{
    const int N = 512;
    __shared__ float As[2][128][20];
    __shared__ float Bs[2][16][136];

    const int tid  = threadIdx.x;
    const int warp = tid >> 5;
    const int lane = tid & 31;
    const int g = lane >> 2;
    const int t = lane & 3;

    const int rowBase = blockIdx.y * 128;
    const int colBase = blockIdx.x * 128;
    const int wm = (warp & 3) * 32;
    const int wn = (warp >> 2) * 64;

    float acc[2][8][4];
#pragma unroll
    for (int mt = 0; mt < 2; mt++)
#pragma unroll
        for (int nt = 0; nt < 8; nt++)
#pragma unroll
            for (int i = 0; i < 4; i++) acc[mt][nt][i] = 0.f;

    const int aRow = tid >> 2;
    const int aC4  = (tid & 3) * 4;
    const int bRow = tid >> 5;
    const int bC4  = (tid & 31) * 4;

    const float* Ag  = A + (size_t)(rowBase + aRow) * K + aC4;
    const float* Ag2 = Ag + (size_t)64 * K;
    const float* Bg  = W + (size_t)bRow * N + colBase + bC4;
    const float* Bg2 = Bg + (size_t)8 * N;

    unsigned sA0 = smem_u32(&As[0][aRow][aC4]);
    unsigned sA1 = smem_u32(&As[0][aRow + 64][aC4]);
    unsigned sB0 = smem_u32(&Bs[0][bRow][bC4]);
    unsigned sB1 = smem_u32(&Bs[0][bRow + 8][bC4]);
    const unsigned strideA = 128 * 20 * 4;
    const unsigned strideB = 16 * 136 * 4;

    CP16(sA0, Ag);  CP16(sA1, Ag2);
    CP16(sB0, Bg);  CP16(sB1, Bg2);
    CP_COMMIT();

    const int nIter = K >> 4;
#pragma unroll 1
    for (int it = 0; it < nIter; it++) {
        const int kt = it * 16;
        const int cur = it & 1;
        if (it + 1 < nIter) {
            const unsigned off  = (cur ^ 1) ? strideA : 0;
            const unsigned offB = (cur ^ 1) ? strideB : 0;
            CP16(sA0 + off, Ag + kt + 16);
            CP16(sA1 + off, Ag2 + kt + 16);
            CP16(sB0 + offB, Bg + (size_t)(kt + 16) * N);
            CP16(sB1 + offB, Bg2 + (size_t)(kt + 16) * N);
            CP_COMMIT();
            CP_WAIT1();
        } else {
            CP_WAIT0();
        }
        __syncthreads();

#pragma unroll
        for (int ks = 0; ks < 16; ks += 8) {
            unsigned af[2][4], bf[8][2];
#pragma unroll
            for (int mt = 0; mt < 2; mt++) {
                const int r0 = wm + mt * 16 + g;
                af[mt][0] = f2tf32(As[cur][r0    ][ks + t    ]);
                af[mt][1] = f2tf32(As[cur][r0 + 8][ks + t    ]);
                af[mt][2] = f2tf32(As[cur][r0    ][ks + t + 4]);
                af[mt][3] = f2tf32(As[cur][r0 + 8][ks + t + 4]);
            }
#pragma unroll
            for (int nt = 0; nt < 8; nt++) {
                const int c0 = wn + nt * 8 + g;
                bf[nt][0] = f2tf32(Bs[cur][ks + t    ][c0]);
                bf[nt][1] = f2tf32(Bs[cur][ks + t + 4][c0]);
            }
#pragma unroll
            for (int mt = 0; mt < 2; mt++)
#pragma unroll
                for (int nt = 0; nt < 8; nt++)
                    mma_tf32(acc[mt][nt], af[mt], bf[nt]);
        }
        __syncthreads();
    }

#pragma unroll
    for (int nt = 0; nt < 8; nt++) {
        const int col = colBase + wn + nt * 8 + 2 * t;
        const float bx = bias[col], by = bias[col + 1];
#pragma unroll
        for (int mt = 0; mt < 2; mt++) {
            const int row0 = rowBase + wm + mt * 16 + g;
            float2 o0, o1;
            o0.x = acc[mt][nt][0] + bx; o0.y = acc[mt][nt][1] + by;
            o1.x = acc[mt][nt][2] + bx; o1.y = acc[mt][nt][3] + by;
            *reinterpret_cast<float2*>(&C[(size_t)row0 * N + col])       = o0;
            *reinterpret_cast<float2*>(&C[(size_t)(row0 + 8) * N + col]) = o1;
        }
    }
}

// ---------------- kv accumulate via tensor cores (unchanged from round 4) ----------------
__global__ __launch_bounds__(128) void kv_accum_kernel(
    const float* __restrict__ xmid, const float* __restrict__ Wk,
    const float* __restrict__ Wv)
{
    const int split = blockIdx.x;
    const int h = blockIdx.y;
    const int b = blockIdx.z;
    const int bh = b * HEADS + h;
    const int tid = threadIdx.x;
    const int w = tid >> 5;
    const int lane = tid & 31;
    const int g = lane >> 2;
    const int t = lane & 3;

    __shared__ float Ws[64][104];
    __shared__ float Xs[64][68];
    __shared__ float Es[32][68];
    __shared__ float Vs[64][72];

    for (int idx = tid; idx < 64 * 32; idx += 128) Ws[idx >> 5][idx & 31] = tf32r(Wk[idx]);
    for (int idx = tid; idx < 64 * 64; idx += 128) Ws[idx >> 6][32 + (idx & 63)] = tf32r(Wv[idx]);
    __syncthreads();

    unsigned bfw[3][8][2];
#pragma unroll
    for (int nt = 0; nt < 3; nt++)
#pragma unroll
        for (int ks = 0; ks < 8; ks++) {
            const int c0 = 24 * w + nt * 8 + g;
            bfw[nt][ks][0] = __float_as_uint(Ws[8 * ks + t    ][c0]);
            bfw[nt][ks][1] = __float_as_uint(Ws[8 * ks + t + 4][c0]);
        }

    float accS1[2][2][4];
#pragma unroll
    for (int mt = 0; mt < 2; mt++)
#pragma unroll
        for (int nt = 0; nt < 2; nt++)
#pragma unroll
            for (int i = 0; i < 4; i++) accS1[mt][nt][i] = 0.f;
    float s0acc = 0.f;

#pragma unroll 1
    for (int chunk = 0; chunk < 2; chunk++) {
        const int n0 = split * 128 + chunk * 64;
        __syncthreads();

        for (int idx = tid; idx < 64 * 16; idx += 128) {
            int r = idx >> 4, c4 = (idx & 15) * 4;
            float4 v = *reinterpret_cast<const float4*>(
                &xmid[(size_t)(b * SEQ + n0 + r) * DIM + h * DH + c4]);
            *reinterpret_cast<float4*>(&Xs[r][c4]) = tf32r4(v);
        }
        __syncthreads();

        float pacc[4][3][4];
#pragma unroll
        for (int mt = 0; mt < 4; mt++)
#pragma unroll
            for (int nt = 0; nt < 3; nt++)
#pragma unroll
                for (int i = 0; i < 4; i++) pacc[mt][nt][i] = 0.f;

#pragma unroll
        for (int ks = 0; ks < 8; ks++) {
            unsigned af[4][4];
#pragma unroll
            for (int mt = 0; mt < 4; mt++) {
                const int r0 = mt * 16 + g;
                af[mt][0] = __float_as_uint(Xs[r0    ][8 * ks + t    ]);
                af[mt][1] = __float_as_uint(Xs[r0 + 8][8 * ks + t    ]);
                af[mt][2] = __float_as_uint(Xs[r0    ][8 * ks + t + 4]);
                af[mt][3] = __float_as_uint(Xs[r0 + 8][8 * ks + t + 4]);
            }
#pragma unroll
            for (int mt = 0; mt < 4; mt++)
#pragma unroll
                for (int nt = 0; nt < 3; nt++)
                    mma_tf32(pacc[mt][nt], af[mt], bfw[nt][ks]);
        }

#pragma unroll
        for (int mt = 0; mt < 4; mt++)
#pragma unroll
            for (int nt = 0; nt < 3; nt++) {
                const int c0 = 24 * w + nt * 8 + 2 * t;
                const int r0 = mt * 16 + g;
                float v0 = pacc[mt][nt][0], v1 = pacc[mt][nt][1];
                float v2 = pacc[mt][nt][2], v3 = pacc[mt][nt][3];
                if (c0 < 32) {
                    Es[c0    ][r0]     = tf32r(expf(v0));
                    Es[c0 + 1][r0]     = tf32r(expf(v1));
                    Es[c0    ][r0 + 8] = tf32r(expf(v2));
                    Es[c0 + 1][r0 + 8] = tf32r(expf(v3));
                } else {
                    Vs[r0    ][c0 - 32]     = tf32r(v0);
                    Vs[r0    ][c0 - 32 + 1] = tf32r(v1);
                    Vs[r0 + 8][c0 - 32]     = tf32r(v2);
                    Vs[r0 + 8][c0 - 32 + 1] = tf32r(v3);
                }
            }
        __syncthreads();

        if (tid < 32) {
            float s = 0.f;
#pragma unroll
            for (int r = 0; r < 64; r++) s += Es[tid][r];
            s0acc += s;
        }

#pragma unroll
        for (int ks = 0; ks < 8; ks++) {
            unsigned af2[2][4];
#pragma unroll
            for (int mt = 0; mt < 2; mt++) {
                const int r0 = mt * 16 + g;
                af2[mt][0] = __float_as_uint(Es[r0    ][8 * ks + t    ]);
                af2[mt][1] = __float_as_uint(Es[r0 + 8][8 * ks + t    ]);
                af2[mt][2] = __float_as_uint(Es[r0    ][8 * ks + t + 4]);
                af2[mt][3] = __float_as_uint(Es[r0 + 8][8 * ks + t + 4]);
            }
#pragma unroll
            for (int nt = 0; nt < 2; nt++) {
                const int c0 = 16 * w + nt * 8 + g;
                unsigned bf2[2];
                bf2[0] = __float_as_uint(Vs[8 * ks + t    ][c0]);
                bf2[1] = __float_as_uint(Vs[8 * ks + t + 4][c0]);
#pragma unroll
                for (int mt = 0; mt < 2; mt++)
                    mma_tf32(accS1[mt][nt], af2[mt], bf2);
            }
        }
    }

    float* base = g_S1p + ((size_t)split * 64 + bh) * (SL * DH);
#pragma unroll
    for (int mt = 0; mt < 2; mt++)
#pragma unroll
        for (int nt = 0; nt < 2; nt++) {
            const int s0 = mt * 16 + g;
            const int c  = 16 * w + nt * 8 + 2 * t;
            base[(s0    ) * DH + c]     = accS1[mt][nt][0];
            base[(s0    ) * DH + c + 1] = accS1[mt][nt][1];
            base[(s0 + 8) * DH + c]     = accS1[mt][nt][2];
            base[(s0 + 8) * DH + c + 1] = accS1[mt][nt][3];
        }
    if (tid < 32) g_S0p[((size_t)split * 64 + bh) * SL + tid] = s0acc;
}

// ---------------- kv finalize ----------------
__global__ __launch_bounds__(256) void kv_final_kernel()
{
    int idx = blockIdx.x * 256 + threadIdx.x;
    if (idx >= 64 * SL * DH) return;
    int bh = idx >> 11;
    int sc = idx & 2047;
    int s  = sc >> 6;
    float s1 = 0.f, s0 = 0.f;
    for (int sp = 0; sp < KV_SPLITS; sp++) {
        s1 += g_S1p[((size_t)sp * 64 + bh) * (SL * DH) + sc];
        s0 += g_S0p[((size_t)sp * 64 + bh) * SL + s];
    }
    g_kv[idx] = s1 / s0;
}

// ---------------- Z prep: Z[b][h*32+s][:] = kv[b,h] (32x64) @ W_out[h*64:(h+1)*64, :] ----------------
// grid (8 colblocks of 64, HEADS, BATCH), 256 threads. Full fp32.
__global__ __launch_bounds__(256) void zprep_kernel(const float* __restrict__ W_out)
{
    const int cb = blockIdx.x;      // 64 output cols
    const int h  = blockIdx.y;
    const int b  = blockIdx.z;
    const int bh = b * HEADS + h;
    const int tid = threadIdx.x;

    __shared__ float kvs[32][64];
    __shared__ float Wos[64][64];

    for (int idx = tid; idx < SL * DH; idx += 256)
        kvs[idx >> 6][idx & 63] = g_kv[(size_t)bh * (SL * DH) + idx];
    for (int idx = tid; idx < 64 * 64; idx += 256) {
        int r = idx >> 6, c = idx & 63;
        Wos[r][c] = W_out[(size_t)(h * DH + r) * DIM + cb * 64 + c];
    }
    __syncthreads();

    for (int idx = tid; idx < SL * 64; idx += 256) {
        int s = idx >> 6, c = idx & 63;
        float d = 0.f;
#pragma unroll
        for (int k = 0; k < 64; k++) d = fmaf(kvs[s][k], Wos[k][c], d);
        g_Z[((size_t)b * QDIM + h * SL + s) * DIM + cb * 64 + c] = d;
    }
}

// ---------------- q projection + softmax -> g_q (N x 256) ----------------
__global__ __launch_bounds__(128) void qproj_kernel(
    const float* __restrict__ xmid, const float* __restrict__ Wq)
{
    const int tile = blockIdx.x;
    const int h = blockIdx.y;
    const int b = blockIdx.z;
    const int tid = threadIdx.x;
    const int w = tid >> 5;
    const int lane = tid & 31;
    const int g = lane >> 2;
    const int t = lane & 3;
    const int n0 = tile * 64;

    __shared__ float Xs[64][68];
    __shared__ float Wqs[64][40];
    __shared__ float Qs[64][36];

    for (int idx = tid; idx < 64 * 16; idx += 128) {
        int r = idx >> 4, c4 = (idx & 15) * 4;
        float4 v = *reinterpret_cast<const float4*>(
            &xmid[(size_t)(b * SEQ + n0 + r) * DIM + h * DH + c4]);
        *reinterpret_cast<float4*>(&Xs[r][c4]) = tf32r4(v);
    }
    for (int idx = tid; idx < 64 * 32; idx += 128)
        Wqs[idx >> 5][idx & 31] = tf32r(Wq[idx]);
    __syncthreads();

    {
        float qacc[4][4];
#pragma unroll
        for (int nt = 0; nt < 4; nt++)
#pragma unroll
            for (int i = 0; i < 4; i++) qacc[nt][i] = 0.f;

#pragma unroll
        for (int ks = 0; ks < 8; ks++) {
            const int r0 = 16 * w + g;
            unsigned af[4];
            af[0] = __float_as_uint(Xs[r0    ][8 * ks + t    ]);
            af[1] = __float_as_uint(Xs[r0 + 8][8 * ks + t    ]);
            af[2] = __float_as_uint(Xs[r0    ][8 * ks + t + 4]);
            af[3] = __float_as_uint(Xs[r0 + 8][8 * ks + t + 4]);
#pragma unroll
            for (int nt = 0; nt < 4; nt++) {
                unsigned bf[2];
                bf[0] = __float_as_uint(Wqs[8 * ks + t    ][nt * 8 + g]);
                bf[1] = __float_as_uint(Wqs[8 * ks + t + 4][nt * 8 + g]);
                mma_tf32(qacc[nt], af, bf);
            }
        }
#pragma unroll
        for (int nt = 0; nt < 4; nt++) {
            const int r0 = 16 * w + g, c0 = nt * 8 + 2 * t;
            Qs[r0    ][c0]     = qacc[nt][0];
            Qs[r0    ][c0 + 1] = qacc[nt][1];
            Qs[r0 + 8][c0]     = qacc[nt][2];
            Qs[r0 + 8][c0 + 1] = qacc[nt][3];
        }
    }
    __syncthreads();

    // softmax over slice dim (one token per thread), then direct global store
    if (tid < 64) {
        float m = Qs[tid][0];
#pragma unroll
        for (int s = 1; s < 32; s++) m = fmaxf(m, Qs[tid][s]);
        float e[32], sum = 0.f;
#pragma unroll
        for (int s = 0; s < 32; s++) { e[s] = expf(Qs[tid][s] - m); sum += e[s]; }
        float inv = 1.f / sum;
#pragma unroll
        for (int s = 0; s < 32; s++) Qs[tid][s] = e[s] * inv;
    }
    __syncthreads();

    // coalesced store: g_q[n][h*32+s]
    for (int idx = tid; idx < 64 * 8; idx += 128) {
        int r = idx >> 3, c4 = (idx & 7) * 4;
        float4 v = *reinterpret_cast<const float4*>(&Qs[r][c4]);
        *reinterpret_cast<float4*>(&g_q[(size_t)(b * SEQ + n0 + r) * QDIM + h * SL + c4]) = v;
    }
}

// ---------------- launch ----------------
extern "C" void kernel_launch(void* const* d_in, const int* in_sizes, int n_in,
                              void* d_out, int out_size)
{
    const float* x     = (const float*)d_in[0];
    const float* W_in  = (const float*)d_in[1];
    const float* b_in  = (const float*)d_in[2];
    const float* Wq    = (const float*)d_in[3];
    const float* Wk    = (const float*)d_in[4];
    const float* Wv    = (const float*)d_in[5];
    const float* W_out = (const float*)d_in[6];
    const float* b_out = (const float*)d_in[7];
    float* out = (float*)d_out;

    float *xmid, *q, *Z;
    cudaGetSymbolAddress((void**)&xmid, g_xmid);
    cudaGetSymbolAddress((void**)&q, g_q);
    cudaGetSymbolAddress((void**)&Z, g_Z);

    // 1) x_mid = x @ W_in + b_in   (K=512)
    dim3 gemmGrid(DIM / 128, MTOT / 128);
    tf32gemm_bias_kernel<<<gemmGrid, 256>>>(x, W_in, b_in, xmid, DIM);

    // 2) kv split partials
    dim3 kvGrid(KV_SPLITS, HEADS, BATCH);
    kv_accum_kernel<<<kvGrid, 128>>>(xmid, Wk, Wv);

    // 3) kv finalize
    kv_final_kernel<<<(64 * SL * DH + 255) / 256, 256>>>();

    // 4) Z = kv @ W_out  (per batch-head, fp32)
    dim3 zGrid(DIM / 64, HEADS, BATCH);
    zprep_kernel<<<zGrid, 256>>>(W_out);

    // 5) Q = softmax(x_mid @ Wq)  -> g_q (N x 256)
    dim3 qGrid(SEQ / 64, HEADS, BATCH);
    qproj_kernel<<<qGrid, 128>>>(xmid, Wq);

    // 6) out = Q @ Z_b + b_out    (K=256, per-batch Z)
    dim3 g2(DIM / 128, SEQ / 128);
    for (int b = 0; b < BATCH; b++) {
        tf32gemm_bias_kernel<<<g2, 256>>>(
            q + (size_t)b * SEQ * QDIM,
            Z + (size_t)b * QDIM * DIM,
            b_out,
            out + (size_t)b * SEQ * DIM,
            QDIM);
    }
}

// round 6
// speedup vs baseline: 2.8751x; 1.0086x over previous
#include <cuda_runtime.h>
#include <cuda_bf16.h>
#include <math.h>

#define BATCH 8
#define SEQ   8192
#define DIM   512
#define HEADS 8
#define DH    64
#define SL    32
#define MTOT  (BATCH * SEQ)
#define KV_SPLITS 64
#define QDIM  (HEADS * SL)        // 256

// ---------------- device scratch ----------------
__device__ float g_xmid[(size_t)MTOT * DIM];
__device__ float g_q   [(size_t)MTOT * QDIM];
__device__ float g_S1p [(size_t)KV_SPLITS * 64 * SL * DH];
__device__ float g_S0p [(size_t)KV_SPLITS * 64 * SL];
__device__ float g_kv  [(size_t)64 * SL * DH];
__device__ float g_Z   [(size_t)BATCH * QDIM * DIM];

__device__ __forceinline__ unsigned f2tf32(float f) {
    unsigned u;
    asm("cvt.rna.tf32.f32 %0, %1;" : "=r"(u) : "f"(f));
    return u;
}
__device__ __forceinline__ float tf32r(float f) { return __uint_as_float(f2tf32(f)); }
__device__ __forceinline__ float4 tf32r4(float4 v) {
    float4 o; o.x = tf32r(v.x); o.y = tf32r(v.y); o.z = tf32r(v.z); o.w = tf32r(v.w);
    return o;
}
__device__ __forceinline__ void mma_tf32(float* c, const unsigned* a, const unsigned* b) {
    asm volatile(
        "mma.sync.aligned.m16n8k8.row.col.f32.tf32.tf32.f32 "
        "{%0,%1,%2,%3}, {%4,%5,%6,%7}, {%8,%9}, {%0,%1,%2,%3};"
        : "+f"(c[0]), "+f"(c[1]), "+f"(c[2]), "+f"(c[3])
        : "r"(a[0]), "r"(a[1]), "r"(a[2]), "r"(a[3]), "r"(b[0]), "r"(b[1]));
}

__device__ __forceinline__ unsigned smem_u32(const void* p) {
    return (unsigned)__cvta_generic_to_shared(p);
}
#define CP16(dst, src) asm volatile("cp.async.cg.shared.global [%0], [%1], 16;" :: "r"(dst), "l"(src))
#define CP_COMMIT()    asm volatile("cp.async.commit_group;")
#define CP_WAIT1()     asm volatile("cp.async.wait_group 1;")
#define CP_WAIT0()     asm volatile("cp.async.wait_group 0;")

// ---------------- TF32 GEMM, 128x128 tile, BK=16, cp.async 2-stage, batched via blockIdx.z ----
__global__ __launch_bounds__(256) void tf32gemm_bias_kernel(
    const float* __restrict__ A, const float* __restrict__ W,
    const float* __restrict__ bias, float* __restrict__ C, int K,
    size_t zStrideA, size_t zStrideW, size_t zStrideC)
{
    const int N = 512;
    __shared__ float As[2][128][20];
    __shared__ float Bs[2][16][136];

    const int tid  = threadIdx.x;
    const int warp = tid >> 5;
    const int lane = tid & 31;
    const int g = lane >> 2;
    const int t = lane & 3;

    const int rowBase = blockIdx.y * 128;
    const int colBase = blockIdx.x * 128;
    const int wm = (warp & 3) * 32;
    const int wn = (warp >> 2) * 64;

    A += zStrideA * blockIdx.z;
    W += zStrideW * blockIdx.z;
    C += zStrideC * blockIdx.z;

    float acc[2][8][4];
#pragma unroll
    for (int mt = 0; mt < 2; mt++)
#pragma unroll
        for (int nt = 0; nt < 8; nt++)
#pragma unroll
            for (int i = 0; i < 4; i++) acc[mt][nt][i] = 0.f;

    const int aRow = tid >> 2;
    const int aC4  = (tid & 3) * 4;
    const int bRow = tid >> 5;
    const int bC4  = (tid & 31) * 4;

    const float* Ag  = A + (size_t)(rowBase + aRow) * K + aC4;
    const float* Ag2 = Ag + (size_t)64 * K;
    const float* Bg  = W + (size_t)bRow * N + colBase + bC4;
    const float* Bg2 = Bg + (size_t)8 * N;

    unsigned sA0 = smem_u32(&As[0][aRow][aC4]);
    unsigned sA1 = smem_u32(&As[0][aRow + 64][aC4]);
    unsigned sB0 = smem_u32(&Bs[0][bRow][bC4]);
    unsigned sB1 = smem_u32(&Bs[0][bRow + 8][bC4]);
    const unsigned strideA = 128 * 20 * 4;
    const unsigned strideB = 16 * 136 * 4;

    CP16(sA0, Ag);  CP16(sA1, Ag2);
    CP16(sB0, Bg);  CP16(sB1, Bg2);
    CP_COMMIT();

    const int nIter = K >> 4;
#pragma unroll 1
    for (int it = 0; it < nIter; it++) {
        const int kt = it * 16;
        const int cur = it & 1;
        if (it + 1 < nIter) {
            const unsigned off  = (cur ^ 1) ? strideA : 0;
            const unsigned offB = (cur ^ 1) ? strideB : 0;
            CP16(sA0 + off, Ag + kt + 16);
            CP16(sA1 + off, Ag2 + kt + 16);
            CP16(sB0 + offB, Bg + (size_t)(kt + 16) * N);
            CP16(sB1 + offB, Bg2 + (size_t)(kt + 16) * N);
            CP_COMMIT();
            CP_WAIT1();
        } else {
            CP_WAIT0();
        }
        __syncthreads();

#pragma unroll
        for (int ks = 0; ks < 16; ks += 8) {
            unsigned af[2][4], bf[8][2];
#pragma unroll
            for (int mt = 0; mt < 2; mt++) {
                const int r0 = wm + mt * 16 + g;
                af[mt][0] = f2tf32(As[cur][r0    ][ks + t    ]);
                af[mt][1] = f2tf32(As[cur][r0 + 8][ks + t    ]);
                af[mt][2] = f2tf32(As[cur][r0    ][ks + t + 4]);
                af[mt][3] = f2tf32(As[cur][r0 + 8][ks + t + 4]);
            }
#pragma unroll
            for (int nt = 0; nt < 8; nt++) {
                const int c0 = wn + nt * 8 + g;
                bf[nt][0] = f2tf32(Bs[cur][ks + t    ][c0]);
                bf[nt][1] = f2tf32(Bs[cur][ks + t + 4][c0]);
            }
#pragma unroll
            for (int mt = 0; mt < 2; mt++)
#pragma unroll
                for (int nt = 0; nt < 8; nt++)
                    mma_tf32(acc[mt][nt], af[mt], bf[nt]);
        }
        __syncthreads();
    }

#pragma unroll
    for (int nt = 0; nt < 8; nt++) {
        const int col = colBase + wn + nt * 8 + 2 * t;
        const float bx = bias[col], by = bias[col + 1];
#pragma unroll
        for (int mt = 0; mt < 2; mt++) {
            const int row0 = rowBase + wm + mt * 16 + g;
            float2 o0, o1;
            o0.x = acc[mt][nt][0] + bx; o0.y = acc[mt][nt][1] + by;
            o1.x = acc[mt][nt][2] + bx; o1.y = acc[mt][nt][3] + by;
            *reinterpret_cast<float2*>(&C[(size_t)row0 * N + col])       = o0;
            *reinterpret_cast<float2*>(&C[(size_t)(row0 + 8) * N + col]) = o1;
        }
    }
}

// ---------------- Fused kv + q kernel ----------------
// grid (KV_SPLITS, HEADS, BATCH), 128 threads (4 warps). 128 tokens per block (2 chunks of 64).
// Per chunk: P = X(64x64) @ [Wq|Wk|Wv](64x128) via mma.
//   warp0 -> Q cols (0-31): softmax rows -> g_q
//   warp1 -> K cols (32-63): exp -> Es transposed
//   warps2,3 -> V cols (64-127) -> Vs
// Then S1 += Es @ Vs (mma), S0 += col sums of Es.
__global__ __launch_bounds__(128) void kvq_fused_kernel(
    const float* __restrict__ xmid, const float* __restrict__ Wq,
    const float* __restrict__ Wk, const float* __restrict__ Wv)
{
    const int split = blockIdx.x;
    const int h = blockIdx.y;
    const int b = blockIdx.z;
    const int bh = b * HEADS + h;
    const int tid = threadIdx.x;
    const int w = tid >> 5;
    const int lane = tid & 31;
    const int g = lane >> 2;
    const int t = lane & 3;

    __shared__ float Ws[64][136];  // cols 0-31 Wq, 32-63 Wk, 64-127 Wv; stride%32=8 (B-frag ok)
    __shared__ float Xs[64][68];   // stride%32=4 (A-frag ok)
    __shared__ float Es[32][68];   // E transposed [slice][token]
    __shared__ float Vs[64][72];   // [token][channel]
    __shared__ float Qs[64][36];   // q rows for softmax

    for (int idx = tid; idx < 64 * 32; idx += 128) Ws[idx >> 5][idx & 31]        = tf32r(Wq[idx]);
    for (int idx = tid; idx < 64 * 32; idx += 128) Ws[idx >> 5][32 + (idx & 31)] = tf32r(Wk[idx]);
    for (int idx = tid; idx < 64 * 64; idx += 128) Ws[idx >> 6][64 + (idx & 63)] = tf32r(Wv[idx]);
    __syncthreads();

    // weight B-fragments: warp w owns cols [32w, 32w+32) -> 4 nt tiles
    unsigned bfw[4][8][2];
#pragma unroll
    for (int nt = 0; nt < 4; nt++)
#pragma unroll
        for (int ks = 0; ks < 8; ks++) {
            const int c0 = 32 * w + nt * 8 + g;
            bfw[nt][ks][0] = __float_as_uint(Ws[8 * ks + t    ][c0]);
            bfw[nt][ks][1] = __float_as_uint(Ws[8 * ks + t + 4][c0]);
        }

    float accS1[2][2][4];
#pragma unroll
    for (int mt = 0; mt < 2; mt++)
#pragma unroll
        for (int nt = 0; nt < 2; nt++)
#pragma unroll
            for (int i = 0; i < 4; i++) accS1[mt][nt][i] = 0.f;
    float s0acc = 0.f;

#pragma unroll 1
    for (int chunk = 0; chunk < 2; chunk++) {
        const int n0 = split * 128 + chunk * 64;
        __syncthreads();   // Es/Vs/Qs from previous chunk fully consumed

        for (int idx = tid; idx < 64 * 16; idx += 128) {
            int r = idx >> 4, c4 = (idx & 15) * 4;
            float4 v = *reinterpret_cast<const float4*>(
                &xmid[(size_t)(b * SEQ + n0 + r) * DIM + h * DH + c4]);
            *reinterpret_cast<float4*>(&Xs[r][c4]) = tf32r4(v);
        }
        __syncthreads();

        // projection mma: 64 rows (4 mt) x warp's 32 cols (4 nt), k=64
        float pacc[4][4][4];
#pragma unroll
        for (int mt = 0; mt < 4; mt++)
#pragma unroll
            for (int nt = 0; nt < 4; nt++)
#pragma unroll
                for (int i = 0; i < 4; i++) pacc[mt][nt][i] = 0.f;

#pragma unroll
        for (int ks = 0; ks < 8; ks++) {
            unsigned af[4][4];
#pragma unroll
            for (int mt = 0; mt < 4; mt++) {
                const int r0 = mt * 16 + g;
                af[mt][0] = __float_as_uint(Xs[r0    ][8 * ks + t    ]);
                af[mt][1] = __float_as_uint(Xs[r0 + 8][8 * ks + t    ]);
                af[mt][2] = __float_as_uint(Xs[r0    ][8 * ks + t + 4]);
                af[mt][3] = __float_as_uint(Xs[r0 + 8][8 * ks + t + 4]);
            }
#pragma unroll
            for (int mt = 0; mt < 4; mt++)
#pragma unroll
                for (int nt = 0; nt < 4; nt++)
                    mma_tf32(pacc[mt][nt], af[mt], bfw[nt][ks]);
        }

        // epilogue by warp role
#pragma unroll
        for (int mt = 0; mt < 4; mt++)
#pragma unroll
            for (int nt = 0; nt < 4; nt++) {
                const int c0 = 32 * w + nt * 8 + 2 * t;
                const int r0 = mt * 16 + g;
                float v0 = pacc[mt][nt][0], v1 = pacc[mt][nt][1];
                float v2 = pacc[mt][nt][2], v3 = pacc[mt][nt][3];
                if (w == 0) {                       // Q raw
                    Qs[r0    ][c0]     = v0;
                    Qs[r0    ][c0 + 1] = v1;
                    Qs[r0 + 8][c0]     = v2;
                    Qs[r0 + 8][c0 + 1] = v3;
                } else if (w == 1) {                // E = exp(K), transposed
                    const int s = c0 - 32;
                    Es[s    ][r0]     = tf32r(expf(v0));
                    Es[s + 1][r0]     = tf32r(expf(v1));
                    Es[s    ][r0 + 8] = tf32r(expf(v2));
                    Es[s + 1][r0 + 8] = tf32r(expf(v3));
                } else {                            // V
                    const int c = c0 - 64;
                    Vs[r0    ][c]     = tf32r(v0);
                    Vs[r0    ][c + 1] = tf32r(v1);
                    Vs[r0 + 8][c]     = tf32r(v2);
                    Vs[r0 + 8][c + 1] = tf32r(v3);
                }
            }
        __syncthreads();

        // softmax over slice dim (one token per thread)
        if (tid < 64) {
            float m = Qs[tid][0];
#pragma unroll
            for (int s = 1; s < 32; s++) m = fmaxf(m, Qs[tid][s]);
            float e[32], sum = 0.f;
#pragma unroll
            for (int s = 0; s < 32; s++) { e[s] = expf(Qs[tid][s] - m); sum += e[s]; }
            float inv = 1.f / sum;
#pragma unroll
            for (int s = 0; s < 32; s++) Qs[tid][s] = e[s] * inv;
        }

        // S0: column sums of E
        if (tid >= 64 && tid < 96) {
            const int s = tid - 64;
            float acc0 = 0.f;
#pragma unroll
            for (int r = 0; r < 64; r++) acc0 += Es[s][r];
            s0acc += acc0;
        }
        __syncthreads();

        // coalesced store of softmaxed Q: g_q[n][h*32+s]
        for (int idx = tid; idx < 64 * 8; idx += 128) {
            int r = idx >> 3, c4 = (idx & 7) * 4;
            float4 v = *reinterpret_cast<const float4*>(&Qs[r][c4]);
            *reinterpret_cast<float4*>(
                &g_q[(size_t)(b * SEQ + n0 + r) * QDIM + h * SL + c4]) = v;
        }

        // S1 += Es(32x64tok) @ Vs(64tok x 64); warp w: cols [16w, 16w+16)
#pragma unroll
        for (int ks = 0; ks < 8; ks++) {
            unsigned af2[2][4];
#pragma unroll
            for (int mt = 0; mt < 2; mt++) {
                const int r0 = mt * 16 + g;
                af2[mt][0] = __float_as_uint(Es[r0    ][8 * ks + t    ]);
                af2[mt][1] = __float_as_uint(Es[r0 + 8][8 * ks + t    ]);
                af2[mt][2] = __float_as_uint(Es[r0    ][8 * ks + t + 4]);
                af2[mt][3] = __float_as_uint(Es[r0 + 8][8 * ks + t + 4]);
            }
#pragma unroll
            for (int nt = 0; nt < 2; nt++) {
                const int c0 = 16 * w + nt * 8 + g;
                unsigned bf2[2];
                bf2[0] = __float_as_uint(Vs[8 * ks + t    ][c0]);
                bf2[1] = __float_as_uint(Vs[8 * ks + t + 4][c0]);
#pragma unroll
                for (int mt = 0; mt < 2; mt++)
                    mma_tf32(accS1[mt][nt], af2[mt], bf2);
            }
        }
    }

    float* base = g_S1p + ((size_t)split * 64 + bh) * (SL * DH);
#pragma unroll
    for (int mt = 0; mt < 2; mt++)
#pragma unroll
        for (int nt = 0; nt < 2; nt++) {
            const int s0 = mt * 16 + g;
            const int c  = 16 * w + nt * 8 + 2 * t;
            base[(s0    ) * DH + c]     = accS1[mt][nt][0];
            base[(s0    ) * DH + c + 1] = accS1[mt][nt][1];
            base[(s0 + 8) * DH + c]     = accS1[mt][nt][2];
            base[(s0 + 8) * DH + c + 1] = accS1[mt][nt][3];
        }
    if (tid >= 64 && tid < 96)
        g_S0p[((size_t)split * 64 + bh) * SL + (tid - 64)] = s0acc;
}

// ---------------- kv finalize ----------------
__global__ __launch_bounds__(256) void kv_final_kernel()
{
    int idx = blockIdx.x * 256 + threadIdx.x;
    if (idx >= 64 * SL * DH) return;
    int bh = idx >> 11;
    int sc = idx & 2047;
    int s  = sc >> 6;
    float s1 = 0.f, s0 = 0.f;
    for (int sp = 0; sp < KV_SPLITS; sp++) {
        s1 += g_S1p[((size_t)sp * 64 + bh) * (SL * DH) + sc];
        s0 += g_S0p[((size_t)sp * 64 + bh) * SL + s];
    }
    g_kv[idx] = s1 / s0;
}

// ---------------- Z prep ----------------
__global__ __launch_bounds__(256) void zprep_kernel(const float* __restrict__ W_out)
{
    const int cb = blockIdx.x;
    const int h  = blockIdx.y;
    const int b  = blockIdx.z;
    const int bh = b * HEADS + h;
    const int tid = threadIdx.x;

    __shared__ float kvs[32][64];
    __shared__ float Wos[64][64];

    for (int idx = tid; idx < SL * DH; idx += 256)
        kvs[idx >> 6][idx & 63] = g_kv[(size_t)bh * (SL * DH) + idx];
    for (int idx = tid; idx < 64 * 64; idx += 256) {
        int r = idx >> 6, c = idx & 63;
        Wos[r][c] = W_out[(size_t)(h * DH + r) * DIM + cb * 64 + c];
    }
    __syncthreads();

    for (int idx = tid; idx < SL * 64; idx += 256) {
        int s = idx >> 6, c = idx & 63;
        float d = 0.f;
#pragma unroll
        for (int k = 0; k < 64; k++) d = fmaf(kvs[s][k], Wos[k][c], d);
        g_Z[((size_t)b * QDIM + h * SL + s) * DIM + cb * 64 + c] = d;
    }
}

// ---------------- launch ----------------
extern "C" void kernel_launch(void* const* d_in, const int* in_sizes, int n_in,
                              void* d_out, int out_size)
{
    const float* x     = (const float*)d_in[0];
    const float* W_in  = (const float*)d_in[1];
    const float* b_in  = (const float*)d_in[2];
    const float* Wq    = (const float*)d_in[3];
    const float* Wk    = (const float*)d_in[4];
    const float* Wv    = (const float*)d_in[5];
    const float* W_out = (const float*)d_in[6];
    const float* b_out = (const float*)d_in[7];
    float* out = (float*)d_out;

    float *xmid, *q, *Z;
    cudaGetSymbolAddress((void**)&xmid, g_xmid);
    cudaGetSymbolAddress((void**)&q, g_q);
    cudaGetSymbolAddress((void**)&Z, g_Z);

    // 1) x_mid = x @ W_in + b_in   (K=512)
    dim3 g1(DIM / 128, MTOT / 128, 1);
    tf32gemm_bias_kernel<<<g1, 256>>>(x, W_in, b_in, xmid, DIM, 0, 0, 0);

    // 2) fused: q-softmax -> g_q, kv split partials -> g_S1p/g_S0p
    dim3 kvGrid(KV_SPLITS, HEADS, BATCH);
    kvq_fused_kernel<<<kvGrid, 128>>>(xmid, Wq, Wk, Wv);

    // 3) kv finalize
    kv_final_kernel<<<(64 * SL * DH + 255) / 256, 256>>>();

    // 4) Z = kv @ W_out
    dim3 zGrid(DIM / 64, HEADS, BATCH);
    zprep_kernel<<<zGrid, 256>>>(W_out);

    // 5) out = Q @ Z_b + b_out    (K=256, batched over z)
    dim3 g2(DIM / 128, SEQ / 128, BATCH);
    tf32gemm_bias_kernel<<<g2, 256>>>(q, Z, b_out, out, QDIM,
                                      (size_t)SEQ * QDIM,
                                      (size_t)QDIM * DIM,
                                      (size_t)SEQ * DIM);
}